// round 1
// baseline (speedup 1.0000x reference)
#include <cuda_runtime.h>

#define ROWS 8
#define THREADS 512
#define D 4096

__global__ __launch_bounds__(THREADS, 1)
void bh_fused_kernel(const float* __restrict__ x,
                     const float* __restrict__ innerB,
                     const float* __restrict__ finalB,
                     float* __restrict__ out)
{
    extern __shared__ float sd[];   // ROWS * D floats = 131072 bytes
    const int tid = threadIdx.x;
    const size_t row0 = (size_t)blockIdx.x * ROWS;

    // ---------------- load ROWS rows (coalesced float4) ----------------
    {
        const float4* gx = reinterpret_cast<const float4*>(x + row0 * D);
        float4* s4 = reinterpret_cast<float4*>(sd);
        #pragma unroll
        for (int k = 0; k < (ROWS * D / 4) / THREADS; k++)
            s4[tid + k * THREADS] = gx[tid + k * THREADS];
    }
    __syncthreads();

    const int g  = tid >> 3;         // group 0..63 (8 threads per group)
    const int ob = (tid & 7) * 8;    // output-col base within group

    #pragma unroll 1
    for (int stage = 0; stage < 2; stage++) {
        // ------------- block-diagonal 64x64 matmul (in smem) -------------
        const float* B = innerB + ((size_t)stage * 64 + g) * 64 * 64;

        float acc[ROWS][8];
        #pragma unroll
        for (int r = 0; r < ROWS; r++)
            #pragma unroll
            for (int o = 0; o < 8; o++)
                acc[r][o] = 0.0f;

        #pragma unroll 1
        for (int j = 0; j < 64; j += 4) {
            float4 xv[ROWS];
            #pragma unroll
            for (int r = 0; r < ROWS; r++)
                xv[r] = *reinterpret_cast<const float4*>(&sd[r * D + g * 64 + j]);
            #pragma unroll
            for (int jj = 0; jj < 4; jj++) {
                const float4 b0 = *reinterpret_cast<const float4*>(&B[(j + jj) * 64 + ob]);
                const float4 b1 = *reinterpret_cast<const float4*>(&B[(j + jj) * 64 + ob + 4]);
                #pragma unroll
                for (int r = 0; r < ROWS; r++) {
                    const float xs = (jj == 0) ? xv[r].x : (jj == 1) ? xv[r].y
                                   : (jj == 2) ? xv[r].z : xv[r].w;
                    acc[r][0] += xs * b0.x; acc[r][1] += xs * b0.y;
                    acc[r][2] += xs * b0.z; acc[r][3] += xs * b0.w;
                    acc[r][4] += xs * b1.x; acc[r][5] += xs * b1.y;
                    acc[r][6] += xs * b1.z; acc[r][7] += xs * b1.w;
                }
            }
        }
        __syncthreads();   // all reads of this region done before overwrite
        #pragma unroll
        for (int r = 0; r < ROWS; r++) {
            float4 v0 = make_float4(acc[r][0], acc[r][1], acc[r][2], acc[r][3]);
            float4 v1 = make_float4(acc[r][4], acc[r][5], acc[r][6], acc[r][7]);
            *reinterpret_cast<float4*>(&sd[r * D + g * 64 + ob])     = v0;
            *reinterpret_cast<float4*>(&sd[r * D + g * 64 + ob + 4]) = v1;
        }
        __syncthreads();

        // ---------------- FWHT: h = 1 and h = 2 fused, in registers ----------------
        {
            float4* s4 = reinterpret_cast<float4*>(sd);
            #pragma unroll
            for (int k = 0; k < (ROWS * D / 4) / THREADS; k++) {
                const int idx = tid + k * THREADS;
                float4 v = s4[idx];
                const float p0 = v.x + v.y, p1 = v.x - v.y;
                const float p2 = v.z + v.w, p3 = v.z - v.w;
                s4[idx] = make_float4(p0 + p2, p1 + p3, p0 - p2, p1 - p3);
            }
        }
        __syncthreads();

        // ---------------- FWHT: h = 4 .. 2048, float4 butterflies ----------------
        #pragma unroll
        for (int h = 4; h <= 2048; h <<= 1) {
            #pragma unroll
            for (int k = 0; k < (ROWS * (D / 8)) / THREADS; k++) {
                const int ug = tid + k * THREADS;
                const int r  = ug >> 9;          // 512 float4-pair units per row
                const int u  = ug & 511;
                const int nq  = h >> 2;          // float4 slots per half-block
                const int blk = u / nq;          // compile-time h after unroll -> shifts
                const int pos = u - blk * nq;
                const int i0 = r * D + blk * (2 * h) + pos * 4;
                float4 a = *reinterpret_cast<float4*>(&sd[i0]);
                float4 b = *reinterpret_cast<float4*>(&sd[i0 + h]);
                float4 s = make_float4(a.x + b.x, a.y + b.y, a.z + b.z, a.w + b.w);
                float4 d = make_float4(a.x - b.x, a.y - b.y, a.z - b.z, a.w - b.w);
                if (h == 2048) {                 // fold the 1/sqrt(4096) scale in
                    const float scl = 1.0f / 64.0f;
                    s.x *= scl; s.y *= scl; s.z *= scl; s.w *= scl;
                    d.x *= scl; d.y *= scl; d.z *= scl; d.w *= scl;
                }
                *reinterpret_cast<float4*>(&sd[i0])     = s;
                *reinterpret_cast<float4*>(&sd[i0 + h]) = d;
            }
            __syncthreads();
        }
    }

    // ---------------- final block-diag 128 x (32x32) matmul -> GMEM ----------------
    {
        const int rect = tid >> 2;        // 0..127 (4 threads per rect)
        const int ob2  = (tid & 3) * 8;   // output-col base within rect
        const float* B = finalB + (size_t)rect * 32 * 32;

        float acc[ROWS][8];
        #pragma unroll
        for (int r = 0; r < ROWS; r++)
            #pragma unroll
            for (int o = 0; o < 8; o++)
                acc[r][o] = 0.0f;

        #pragma unroll 1
        for (int j = 0; j < 32; j += 4) {
            float4 xv[ROWS];
            #pragma unroll
            for (int r = 0; r < ROWS; r++)
                xv[r] = *reinterpret_cast<const float4*>(&sd[r * D + rect * 32 + j]);
            #pragma unroll
            for (int jj = 0; jj < 4; jj++) {
                const float4 b0 = *reinterpret_cast<const float4*>(&B[(j + jj) * 32 + ob2]);
                const float4 b1 = *reinterpret_cast<const float4*>(&B[(j + jj) * 32 + ob2 + 4]);
                #pragma unroll
                for (int r = 0; r < ROWS; r++) {
                    const float xs = (jj == 0) ? xv[r].x : (jj == 1) ? xv[r].y
                                   : (jj == 2) ? xv[r].z : xv[r].w;
                    acc[r][0] += xs * b0.x; acc[r][1] += xs * b0.y;
                    acc[r][2] += xs * b0.z; acc[r][3] += xs * b0.w;
                    acc[r][4] += xs * b1.x; acc[r][5] += xs * b1.y;
                    acc[r][6] += xs * b1.z; acc[r][7] += xs * b1.w;
                }
            }
        }
        #pragma unroll
        for (int r = 0; r < ROWS; r++) {
            float4 v0 = make_float4(acc[r][0], acc[r][1], acc[r][2], acc[r][3]);
            float4 v1 = make_float4(acc[r][4], acc[r][5], acc[r][6], acc[r][7]);
            float* op = out + (row0 + r) * D + rect * 32 + ob2;
            *reinterpret_cast<float4*>(op)     = v0;
            *reinterpret_cast<float4*>(op + 4) = v1;
        }
    }
}

extern "C" void kernel_launch(void* const* d_in, const int* in_sizes, int n_in,
                              void* d_out, int out_size) {
    const float* x  = (const float*)d_in[0];   // [4,4096,4096] f32
    const float* iB = (const float*)d_in[1];   // [2,64,64,64]  f32
    const float* fB = (const float*)d_in[2];   // [128,32,32]   f32
    float* out = (float*)d_out;                // [4,4096,4096] f32

    const int smem = ROWS * D * sizeof(float); // 131072 bytes
    cudaFuncSetAttribute(bh_fused_kernel,
                         cudaFuncAttributeMaxDynamicSharedMemorySize, smem);

    const int nrows = 4 * 4096;                // 16384 rows total
    bh_fused_kernel<<<nrows / ROWS, THREADS, smem>>>(x, iB, fB, out);
}

// round 2
// speedup vs baseline: 1.5950x; 1.5950x over previous
#include <cuda_runtime.h>

#define ROWS 8
#define THREADS 512
#define D 4096

typedef unsigned long long u64;

// H-folded, pre-scaled inner matrices: C[s][n] = (B[s][n] @ H64) / 64
__device__ float g_C[2 * 64 * 64 * 64];

__device__ __forceinline__ u64 pack2(float x) {
    u64 r; asm("mov.b64 %0,{%1,%1};" : "=l"(r) : "f"(x)); return r;
}
__device__ __forceinline__ void fma2(u64& d, u64 a, u64 b) {
    asm("fma.rn.f32x2 %0,%1,%2,%3;" : "=l"(d) : "l"(a), "l"(b), "l"(d));
}

// ---------------- prepass: C = (B @ H64) / 64, i.e. fwht64 of each row ----------------
__global__ void prep_kernel(const float* __restrict__ innerB) {
    const int t = blockIdx.x * blockDim.x + threadIdx.x;   // (s*64+n)*64+i, 0..8191
    const float4* src = reinterpret_cast<const float4*>(innerB + (size_t)t * 64);
    float v[64];
    #pragma unroll
    for (int k = 0; k < 16; k++) {
        float4 f = src[k];
        v[4*k] = f.x; v[4*k+1] = f.y; v[4*k+2] = f.z; v[4*k+3] = f.w;
    }
    #pragma unroll
    for (int h = 1; h < 64; h <<= 1)
        #pragma unroll
        for (int m = 0; m < 64; m += 2*h)
            #pragma unroll
            for (int k = 0; k < h; k++) {
                float a = v[m+k], b = v[m+k+h];
                v[m+k] = a + b; v[m+k+h] = a - b;
            }
    float4* dst = reinterpret_cast<float4*>(g_C + (size_t)t * 64);
    const float s = 1.0f / 64.0f;
    #pragma unroll
    for (int k = 0; k < 16; k++)
        dst[k] = make_float4(v[4*k]*s, v[4*k+1]*s, v[4*k+2]*s, v[4*k+3]*s);
}

// ---------------- main fused kernel ----------------
__global__ __launch_bounds__(THREADS, 1)
void bh_fused_kernel(const float* __restrict__ x,
                     const float* __restrict__ finalB,
                     float* __restrict__ out)
{
    extern __shared__ float sd[];   // ROWS * D floats = 131072 bytes
    const int tid = threadIdx.x;
    const size_t row0 = (size_t)blockIdx.x * ROWS;

    // load ROWS rows (coalesced float4)
    {
        const float4* gx = reinterpret_cast<const float4*>(x + row0 * D);
        float4* s4 = reinterpret_cast<float4*>(sd);
        #pragma unroll
        for (int k = 0; k < (ROWS * D / 4) / THREADS; k++)
            s4[tid + k * THREADS] = gx[tid + k * THREADS];
    }
    __syncthreads();

    const int g  = tid >> 3;         // group 0..63 (8 threads per group)
    const int ob = (tid & 7) * 8;    // output-col base within group

    #pragma unroll 1
    for (int stage = 0; stage < 2; stage++) {
        // ---- block-diag 64x64 matmul with C (inner H64 + scale folded in) ----
        const float* C = g_C + ((size_t)stage * 64 + g) * 64 * 64;

        u64 acc[ROWS][4];
        #pragma unroll
        for (int r = 0; r < ROWS; r++)
            #pragma unroll
            for (int p = 0; p < 4; p++)
                acc[r][p] = 0ull;

        #pragma unroll 1
        for (int j = 0; j < 64; j += 4) {
            float4 xv[ROWS];
            #pragma unroll
            for (int r = 0; r < ROWS; r++)
                xv[r] = *reinterpret_cast<const float4*>(&sd[r * D + g * 64 + j]);
            #pragma unroll
            for (int jj = 0; jj < 4; jj++) {
                const ulonglong2 b01 = *reinterpret_cast<const ulonglong2*>(&C[(j + jj) * 64 + ob]);
                const ulonglong2 b23 = *reinterpret_cast<const ulonglong2*>(&C[(j + jj) * 64 + ob + 4]);
                #pragma unroll
                for (int r = 0; r < ROWS; r++) {
                    const float xs = (jj == 0) ? xv[r].x : (jj == 1) ? xv[r].y
                                   : (jj == 2) ? xv[r].z : xv[r].w;
                    const u64 xs2 = pack2(xs);
                    fma2(acc[r][0], xs2, b01.x);
                    fma2(acc[r][1], xs2, b01.y);
                    fma2(acc[r][2], xs2, b23.x);
                    fma2(acc[r][3], xs2, b23.y);
                }
            }
        }
        __syncthreads();   // all reads of the stage input done before overwrite
        #pragma unroll
        for (int r = 0; r < ROWS; r++) {
            ulonglong2* sp = reinterpret_cast<ulonglong2*>(&sd[r * D + g * 64 + ob]);
            sp[0] = make_ulonglong2(acc[r][0], acc[r][1]);
            sp[1] = make_ulonglong2(acc[r][2], acc[r][3]);
        }
        __syncthreads();

        // ---- outer H64 (stride-64 across blocks), fully register-resident ----
        {
            const int hr = tid >> 6;      // row 0..7
            const int hj = tid & 63;      // within-block column
            float v[64];
            #pragma unroll
            for (int m = 0; m < 64; m++)
                v[m] = sd[hr * D + m * 64 + hj];
            #pragma unroll
            for (int h = 1; h < 64; h <<= 1)
                #pragma unroll
                for (int m = 0; m < 64; m += 2*h)
                    #pragma unroll
                    for (int k = 0; k < h; k++) {
                        float a = v[m+k], b = v[m+k+h];
                        v[m+k] = a + b; v[m+k+h] = a - b;
                    }
            #pragma unroll
            for (int m = 0; m < 64; m++)
                sd[hr * D + m * 64 + hj] = v[m];
        }
        __syncthreads();
    }

    // ---------------- final block-diag 128 x (32x32) matmul -> GMEM ----------------
    {
        const int rect = tid >> 2;        // 0..127 (4 threads per rect)
        const int ob2  = (tid & 3) * 8;   // output-col base within rect
        const float* B = finalB + (size_t)rect * 32 * 32;

        u64 acc[ROWS][4];
        #pragma unroll
        for (int r = 0; r < ROWS; r++)
            #pragma unroll
            for (int p = 0; p < 4; p++)
                acc[r][p] = 0ull;

        #pragma unroll 1
        for (int j = 0; j < 32; j += 4) {
            float4 xv[ROWS];
            #pragma unroll
            for (int r = 0; r < ROWS; r++)
                xv[r] = *reinterpret_cast<const float4*>(&sd[r * D + rect * 32 + j]);
            #pragma unroll
            for (int jj = 0; jj < 4; jj++) {
                const ulonglong2 b01 = *reinterpret_cast<const ulonglong2*>(&B[(j + jj) * 32 + ob2]);
                const ulonglong2 b23 = *reinterpret_cast<const ulonglong2*>(&B[(j + jj) * 32 + ob2 + 4]);
                #pragma unroll
                for (int r = 0; r < ROWS; r++) {
                    const float xs = (jj == 0) ? xv[r].x : (jj == 1) ? xv[r].y
                                   : (jj == 2) ? xv[r].z : xv[r].w;
                    const u64 xs2 = pack2(xs);
                    fma2(acc[r][0], xs2, b01.x);
                    fma2(acc[r][1], xs2, b01.y);
                    fma2(acc[r][2], xs2, b23.x);
                    fma2(acc[r][3], xs2, b23.y);
                }
            }
        }
        #pragma unroll
        for (int r = 0; r < ROWS; r++) {
            ulonglong2* op = reinterpret_cast<ulonglong2*>(out + (row0 + r) * D + rect * 32 + ob2);
            op[0] = make_ulonglong2(acc[r][0], acc[r][1]);
            op[1] = make_ulonglong2(acc[r][2], acc[r][3]);
        }
    }
}

extern "C" void kernel_launch(void* const* d_in, const int* in_sizes, int n_in,
                              void* d_out, int out_size) {
    const float* x  = (const float*)d_in[0];   // [4,4096,4096] f32
    const float* iB = (const float*)d_in[1];   // [2,64,64,64]  f32
    const float* fB = (const float*)d_in[2];   // [128,32,32]   f32
    float* out = (float*)d_out;                // [4,4096,4096] f32

    prep_kernel<<<64, 128>>>(iB);

    const int smem = ROWS * D * sizeof(float); // 131072 bytes
    cudaFuncSetAttribute(bh_fused_kernel,
                         cudaFuncAttributeMaxDynamicSharedMemorySize, smem);
    const int nrows = 4 * 4096;
    bh_fused_kernel<<<nrows / ROWS, THREADS, smem>>>(x, fB, out);
}

// round 3
// speedup vs baseline: 1.7133x; 1.0742x over previous
#include <cuda_runtime.h>

#define ROWS 8
#define THREADS 512
#define D 4096

typedef unsigned long long u64;

// H-folded, pre-scaled inner matrices: C[s][n] = (B[s][n] @ H64) / 64
__device__ float g_C[2 * 64 * 64 * 64];

__device__ __forceinline__ u64 pack2(float x) {
    u64 r; asm("mov.b64 %0,{%1,%1};" : "=l"(r) : "f"(x)); return r;
}
__device__ __forceinline__ void fma2(u64& d, u64 a, u64 b) {
    asm("fma.rn.f32x2 %0,%1,%2,%3;" : "=l"(d) : "l"(a), "l"(b), "l"(d));
}
// bank-conflict-avoiding swizzle: logical (block n, col c) -> physical col
__device__ __forceinline__ int swz(int n, int c) {
    return n * 64 + (c ^ ((n & 7) << 3));
}

// ---------------- prepass: C = (B @ H64) / 64 ----------------
__global__ void prep_kernel(const float* __restrict__ innerB) {
    const int t = blockIdx.x * blockDim.x + threadIdx.x;   // row of a 64x64 block
    const float4* src = reinterpret_cast<const float4*>(innerB + (size_t)t * 64);
    float v[64];
    #pragma unroll
    for (int k = 0; k < 16; k++) {
        float4 f = src[k];
        v[4*k] = f.x; v[4*k+1] = f.y; v[4*k+2] = f.z; v[4*k+3] = f.w;
    }
    #pragma unroll
    for (int h = 1; h < 64; h <<= 1)
        #pragma unroll
        for (int m = 0; m < 64; m += 2*h)
            #pragma unroll
            for (int k = 0; k < h; k++) {
                float a = v[m+k], b = v[m+k+h];
                v[m+k] = a + b; v[m+k+h] = a - b;
            }
    float4* dst = reinterpret_cast<float4*>(g_C + (size_t)t * 64);
    const float s = 1.0f / 64.0f;
    #pragma unroll
    for (int k = 0; k < 16; k++)
        dst[k] = make_float4(v[4*k]*s, v[4*k+1]*s, v[4*k+2]*s, v[4*k+3]*s);
}

// ---------------- main fused kernel ----------------
__global__ __launch_bounds__(THREADS, 1)
void bh_fused_kernel(const float* __restrict__ x,
                     const float* __restrict__ finalB,
                     float* __restrict__ out)
{
    extern __shared__ float sd[];   // ROWS * D floats, swizzled layout
    const int tid = threadIdx.x;
    const size_t row0 = (size_t)blockIdx.x * ROWS;

    // ---- load ROWS rows (coalesced gmem read, swizzled smem store) ----
    {
        const float4* gx = reinterpret_cast<const float4*>(x + row0 * D);
        float4* s4 = reinterpret_cast<float4*>(sd);
        #pragma unroll
        for (int k = 0; k < (ROWS * D / 4) / THREADS; k++) {
            const int f   = tid + k * THREADS;        // global float4 idx in tile
            const int r   = f >> 10;                  // 1024 float4 per row
            const int cq  = f & 1023;
            const int n   = cq >> 4;                  // block
            const int c   = (cq & 15) * 4;            // col within block
            s4[r * 1024 + (swz(n, c) >> 2)] = gx[f];
        }
    }
    __syncthreads();

    const int g  = tid >> 3;         // group 0..63 (8 threads per group)
    const int ob = (tid & 7) * 8;    // output-col base within group
    const int pb = swz(g, ob);       // physical col base for writes (8-aligned)

    #pragma unroll 1
    for (int stage = 0; stage < 2; stage++) {
        // ---- block-diag 64x64 matmul with C (inner H64 + scale folded) ----
        const float* C = g_C + ((size_t)stage * 64 + g) * 64 * 64;

        u64 acc[ROWS][4];
        #pragma unroll
        for (int r = 0; r < ROWS; r++)
            #pragma unroll
            for (int p = 0; p < 4; p++)
                acc[r][p] = 0ull;

        #pragma unroll 1
        for (int j = 0; j < 64; j += 4) {
            const int pj = swz(g, j);                 // physical float4 base
            float4 xv[ROWS];
            #pragma unroll
            for (int r = 0; r < ROWS; r++)
                xv[r] = *reinterpret_cast<const float4*>(&sd[r * D + pj]);
            #pragma unroll
            for (int jj = 0; jj < 4; jj++) {
                const ulonglong2 b01 = *reinterpret_cast<const ulonglong2*>(&C[(j + jj) * 64 + ob]);
                const ulonglong2 b23 = *reinterpret_cast<const ulonglong2*>(&C[(j + jj) * 64 + ob + 4]);
                #pragma unroll
                for (int r = 0; r < ROWS; r++) {
                    const float xs = (jj == 0) ? xv[r].x : (jj == 1) ? xv[r].y
                                   : (jj == 2) ? xv[r].z : xv[r].w;
                    const u64 xs2 = pack2(xs);
                    fma2(acc[r][0], xs2, b01.x);
                    fma2(acc[r][1], xs2, b01.y);
                    fma2(acc[r][2], xs2, b23.x);
                    fma2(acc[r][3], xs2, b23.y);
                }
            }
        }
        __syncthreads();   // all reads of the stage input done before overwrite
        #pragma unroll
        for (int r = 0; r < ROWS; r++) {
            ulonglong2* sp = reinterpret_cast<ulonglong2*>(&sd[r * D + pb]);
            sp[0] = make_ulonglong2(acc[r][0], acc[r][1]);
            sp[1] = make_ulonglong2(acc[r][2], acc[r][3]);
        }
        __syncthreads();

        // ---- outer H64 (stride-64 across blocks), register-resident ----
        {
            const int hr = tid >> 6;      // row 0..7
            const int hj = tid & 63;      // within-block column
            float v[64];
            #pragma unroll
            for (int m = 0; m < 64; m++)
                v[m] = sd[hr * D + m * 64 + (hj ^ ((m & 7) << 3))];
            #pragma unroll
            for (int h = 1; h < 64; h <<= 1)
                #pragma unroll
                for (int m = 0; m < 64; m += 2*h)
                    #pragma unroll
                    for (int k = 0; k < h; k++) {
                        float a = v[m+k], b = v[m+k+h];
                        v[m+k] = a + b; v[m+k+h] = a - b;
                    }
            #pragma unroll
            for (int m = 0; m < 64; m++)
                sd[hr * D + m * 64 + (hj ^ ((m & 7) << 3))] = v[m];
        }
        __syncthreads();
    }

    // ---------------- final block-diag 128 x (32x32) matmul -> GMEM ----------------
    {
        const int rect = tid >> 2;        // 0..127 (4 threads per rect)
        const int ob2  = (tid & 3) * 8;   // output-col base within rect
        const int n    = rect >> 1;       // 64-block containing this rect
        const int cb   = (rect & 1) * 32; // col base of rect within block
        const float* B = finalB + (size_t)rect * 32 * 32;

        u64 acc[ROWS][4];
        #pragma unroll
        for (int r = 0; r < ROWS; r++)
            #pragma unroll
            for (int p = 0; p < 4; p++)
                acc[r][p] = 0ull;

        #pragma unroll 1
        for (int j = 0; j < 32; j += 4) {
            const int pj = swz(n, cb + j);
            float4 xv[ROWS];
            #pragma unroll
            for (int r = 0; r < ROWS; r++)
                xv[r] = *reinterpret_cast<const float4*>(&sd[r * D + pj]);
            #pragma unroll
            for (int jj = 0; jj < 4; jj++) {
                const ulonglong2 b01 = *reinterpret_cast<const ulonglong2*>(&B[(j + jj) * 32 + ob2]);
                const ulonglong2 b23 = *reinterpret_cast<const ulonglong2*>(&B[(j + jj) * 32 + ob2 + 4]);
                #pragma unroll
                for (int r = 0; r < ROWS; r++) {
                    const float xs = (jj == 0) ? xv[r].x : (jj == 1) ? xv[r].y
                                   : (jj == 2) ? xv[r].z : xv[r].w;
                    const u64 xs2 = pack2(xs);
                    fma2(acc[r][0], xs2, b01.x);
                    fma2(acc[r][1], xs2, b01.y);
                    fma2(acc[r][2], xs2, b23.x);
                    fma2(acc[r][3], xs2, b23.y);
                }
            }
        }
        #pragma unroll
        for (int r = 0; r < ROWS; r++) {
            ulonglong2* op = reinterpret_cast<ulonglong2*>(out + (row0 + r) * D + rect * 32 + ob2);
            op[0] = make_ulonglong2(acc[r][0], acc[r][1]);
            op[1] = make_ulonglong2(acc[r][2], acc[r][3]);
        }
    }
}

extern "C" void kernel_launch(void* const* d_in, const int* in_sizes, int n_in,
                              void* d_out, int out_size) {
    const float* x  = (const float*)d_in[0];   // [4,4096,4096] f32
    const float* iB = (const float*)d_in[1];   // [2,64,64,64]  f32
    const float* fB = (const float*)d_in[2];   // [128,32,32]   f32
    float* out = (float*)d_out;                // [4,4096,4096] f32

    prep_kernel<<<64, 128>>>(iB);

    const int smem = ROWS * D * sizeof(float); // 131072 bytes
    cudaFuncSetAttribute(bh_fused_kernel,
                         cudaFuncAttributeMaxDynamicSharedMemorySize, smem);
    const int nrows = 4 * 4096;
    bh_fused_kernel<<<nrows / ROWS, THREADS, smem>>>(x, fB, out);
}